// round 6
// baseline (speedup 1.0000x reference)
#include <cuda_runtime.h>
#include <math.h>

// Problem shape (fixed by the dataset)
#define S_   512
#define N_   512
#define CM_  64
#define CZ_  128
#define H_   8
#define D_   8
#define SN_  (S_*N_)      // 262144 rows of m / out
#define EPS_ 1e-5f

// ---------------------------------------------------------------------------
// Scratch (device globals — no allocation allowed in kernel_launch)
// ---------------------------------------------------------------------------
__device__ float g_v   [SN_*CM_];   // v[j][n][c]   (c = h*8+d)     64MB
__device__ float g_gate[SN_*CM_];   // sigmoid(m@Wg^T)[i][n][c]     64MB
__device__ float g_b   [H_*S_*S_];  // b/w[h][i][j]                  8MB
__device__ float g_go  [SN_*CM_];   // (g*o)[i][n][c]               64MB

// ---------------------------------------------------------------------------
// Kernel A: per-row LayerNorm over CM, then v = mhat@Wv^T, gate = sigmoid(mhat@Wg^T)
// one thread per (s,n) row; W matrices in shared (broadcast reads)
// ---------------------------------------------------------------------------
__global__ void __launch_bounds__(128) k_ln_vg(
    const float* __restrict__ m, const float* __restrict__ lw,
    const float* __restrict__ lb, const float* __restrict__ Wv,
    const float* __restrict__ Wg)
{
    __shared__ float sWv[CM_*CM_];
    __shared__ float sWg[CM_*CM_];
    __shared__ float slw[CM_], slb[CM_];
    int tid = threadIdx.x;
    for (int i = tid; i < CM_*CM_; i += 128) { sWv[i] = Wv[i]; sWg[i] = Wg[i]; }
    if (tid < CM_) { slw[tid] = lw[tid]; slb[tid] = lb[tid]; }
    __syncthreads();

    size_t row = (size_t)blockIdx.x * 128 + tid;
    const float4* src = reinterpret_cast<const float4*>(m + row * CM_);
    float x[CM_];
    float s = 0.f, s2 = 0.f;
#pragma unroll
    for (int i = 0; i < 16; i++) {
        float4 t = src[i];
        x[4*i+0] = t.x; x[4*i+1] = t.y; x[4*i+2] = t.z; x[4*i+3] = t.w;
        s  += t.x + t.y + t.z + t.w;
        s2 += t.x*t.x + t.y*t.y + t.z*t.z + t.w*t.w;
    }
    float mu  = s * (1.f/CM_);
    float inv = rsqrtf(s2 * (1.f/CM_) - mu*mu + EPS_);
#pragma unroll
    for (int i = 0; i < CM_; i++) x[i] = (x[i] - mu) * inv * slw[i] + slb[i];

    float4* ov = reinterpret_cast<float4*>(g_v    + row * CM_);
    float4* og = reinterpret_cast<float4*>(g_gate + row * CM_);
    for (int o = 0; o < CM_; o += 4) {
        float av[4], ag[4];
#pragma unroll
        for (int oo = 0; oo < 4; oo++) {
            const float4* wv = reinterpret_cast<const float4*>(sWv + (o+oo) * CM_);
            const float4* wg = reinterpret_cast<const float4*>(sWg + (o+oo) * CM_);
            float a0 = 0.f, a1 = 0.f;
#pragma unroll
            for (int k = 0; k < 16; k++) {
                float4 w1 = wv[k];
                a0 += x[4*k+0]*w1.x + x[4*k+1]*w1.y + x[4*k+2]*w1.z + x[4*k+3]*w1.w;
                float4 w2 = wg[k];
                a1 += x[4*k+0]*w2.x + x[4*k+1]*w2.y + x[4*k+2]*w2.z + x[4*k+3]*w2.w;
            }
            av[oo] = a0;
            ag[oo] = 1.f / (1.f + __expf(-a1));   // sigmoid
        }
        float4 v4; v4.x = av[0]; v4.y = av[1]; v4.z = av[2]; v4.w = av[3];
        float4 g4; g4.x = ag[0]; g4.y = ag[1]; g4.z = ag[2]; g4.w = ag[3];
        ov[o >> 2] = v4;
        og[o >> 2] = g4;
    }
}

// ---------------------------------------------------------------------------
// Kernel B: b[h][i][j] = LN(z[i][j][:]) . W_b[h][:]   (one warp per (i,j))
// ---------------------------------------------------------------------------
__global__ void __launch_bounds__(256) k_bias(
    const float* __restrict__ z, const float* __restrict__ lw,
    const float* __restrict__ lb, const float* __restrict__ Wb)
{
    __shared__ float sWb[H_*CZ_];
    __shared__ float slw[CZ_], slb[CZ_];
    int tid = threadIdx.x;
    for (int i = tid; i < H_*CZ_; i += 256) sWb[i] = Wb[i];
    if (tid < CZ_) { slw[tid] = lw[tid]; slb[tid] = lb[tid]; }
    __syncthreads();

    int lane = tid & 31;
    size_t row = (size_t)blockIdx.x * 8 + (tid >> 5);   // i*512 + j
    float4 t = reinterpret_cast<const float4*>(z + row * CZ_)[lane];
    float s  = t.x + t.y + t.z + t.w;
    float s2 = t.x*t.x + t.y*t.y + t.z*t.z + t.w*t.w;
#pragma unroll
    for (int o = 16; o; o >>= 1) {
        s  += __shfl_xor_sync(0xffffffffu, s,  o);
        s2 += __shfl_xor_sync(0xffffffffu, s2, o);
    }
    float mu  = s * (1.f/CZ_);
    float inv = rsqrtf(s2 * (1.f/CZ_) - mu*mu + EPS_);
    int c = lane * 4;
    float x0 = (t.x - mu) * inv * slw[c+0] + slb[c+0];
    float x1 = (t.y - mu) * inv * slw[c+1] + slb[c+1];
    float x2 = (t.z - mu) * inv * slw[c+2] + slb[c+2];
    float x3 = (t.w - mu) * inv * slw[c+3] + slb[c+3];

    float p[H_];
#pragma unroll
    for (int h = 0; h < H_; h++) {
        const float* w = sWb + h * CZ_ + c;
        p[h] = x0*w[0] + x1*w[1] + x2*w[2] + x3*w[3];
    }
#pragma unroll
    for (int o = 16; o; o >>= 1) {
#pragma unroll
        for (int h = 0; h < H_; h++)
            p[h] += __shfl_xor_sync(0xffffffffu, p[h], o);
    }
    if (lane < H_) g_b[(size_t)lane * (S_*S_) + row] = p[lane];
}

// ---------------------------------------------------------------------------
// Kernel B2: in-place softmax over j for each (h,i) row of g_b (512 elements)
// one warp per row
// ---------------------------------------------------------------------------
__global__ void __launch_bounds__(256) k_softmax()
{
    int lane = threadIdx.x & 31;
    size_t r = (size_t)blockIdx.x * 8 + (threadIdx.x >> 5);   // h*S + i
    float4* p = reinterpret_cast<float4*>(g_b + r * S_);
    float4 v[4];
    float mx = -1e30f;
#pragma unroll
    for (int q = 0; q < 4; q++) {
        v[q] = p[q*32 + lane];
        mx = fmaxf(mx, fmaxf(fmaxf(v[q].x, v[q].y), fmaxf(v[q].z, v[q].w)));
    }
#pragma unroll
    for (int o = 16; o; o >>= 1) mx = fmaxf(mx, __shfl_xor_sync(0xffffffffu, mx, o));
    float sum = 0.f;
#pragma unroll
    for (int q = 0; q < 4; q++) {
        v[q].x = __expf(v[q].x - mx); v[q].y = __expf(v[q].y - mx);
        v[q].z = __expf(v[q].z - mx); v[q].w = __expf(v[q].w - mx);
        sum += v[q].x + v[q].y + v[q].z + v[q].w;
    }
#pragma unroll
    for (int o = 16; o; o >>= 1) sum += __shfl_xor_sync(0xffffffffu, sum, o);
    float is = 1.f / sum;
#pragma unroll
    for (int q = 0; q < 4; q++) {
        v[q].x *= is; v[q].y *= is; v[q].z *= is; v[q].w *= is;
        p[q*32 + lane] = v[q];
    }
}

// ---------------------------------------------------------------------------
// Kernel C: per head h: O_h[i][nd] = sum_j w[h][i][j] * v[j][n, h*8+d]
//   column index nd = n*8 + d,  nd in [0, N_*D_) = [0, 4096)
// fused epilogue: g_go = gate * O.  Classic 128x64x32 register-blocked SGEMM,
// 8x4 microtile per thread, 256 threads.
// ---------------------------------------------------------------------------
#define BM 128
#define BN 64
#define BK 32
#define ASTR 132   // padded smem stride for A^T (16B aligned, conflict-reduced)

__global__ void __launch_bounds__(256) k_pwa()
{
    __shared__ float As[BK * ASTR];   // As[k][m]
    __shared__ float Bs[BK * BN];     // Bs[k][nd]
    int tid = threadIdx.x;
    int tx  = tid & 15;    // nd groups of 4
    int ty  = tid >> 4;    // i groups of 8
    int h   = blockIdx.z;
    int i0  = blockIdx.y * BM;
    int nd0 = blockIdx.x * BN;        // nd0 < N_*D_ = 4096

    const float* Ag = g_b + (size_t)h * (S_*S_);   // softmaxed weights w[h]

    float acc[8][4];
#pragma unroll
    for (int r = 0; r < 8; r++)
#pragma unroll
        for (int c = 0; c < 4; c++) acc[r][c] = 0.f;

    const float4* As4 = reinterpret_cast<const float4*>(As);
    const float4* Bs4 = reinterpret_cast<const float4*>(Bs);

    for (int kt = 0; kt < S_/BK; kt++) {
        int k0 = kt * BK;
        // stage globals into registers (overlaps with prior tile's compute)
        float4 aR[4], bR[2];
#pragma unroll
        for (int q = 0; q < 4; q++) {
            int f = q*256 + tid;                 // 0..1023 float4 ids (128x8)
            int rA = f >> 3, c4 = f & 7;
            aR[q] = *reinterpret_cast<const float4*>(
                Ag + (size_t)(i0 + rA) * S_ + k0 + c4*4);
        }
#pragma unroll
        for (int q = 0; q < 2; q++) {
            int f = q*256 + tid;                 // 0..511 float4 ids (32x16)
            int rB = f >> 4, c4 = f & 15;
            int nd = nd0 + c4*4;                 // multiple of 4; d in {0,4}
            int n = nd >> 3, d = nd & 7;         // n < 512
            bR[q] = *reinterpret_cast<const float4*>(
                g_v + (size_t)(k0 + rB) * (N_*CM_) + n*CM_ + h*D_ + d);
        }
        __syncthreads();   // previous tile's compute done
#pragma unroll
        for (int q = 0; q < 4; q++) {
            int f = q*256 + tid; int rA = f >> 3, c4 = f & 7;
            As[(c4*4+0)*ASTR + rA] = aR[q].x;
            As[(c4*4+1)*ASTR + rA] = aR[q].y;
            As[(c4*4+2)*ASTR + rA] = aR[q].z;
            As[(c4*4+3)*ASTR + rA] = aR[q].w;
        }
#pragma unroll
        for (int q = 0; q < 2; q++) {
            int f = q*256 + tid; int rB = f >> 4, c4 = f & 15;
            reinterpret_cast<float4*>(Bs)[rB*16 + c4] = bR[q];
        }
        __syncthreads();
#pragma unroll
        for (int k = 0; k < BK; k++) {
            float4 a0 = As4[k*(ASTR/4) + ty*2];
            float4 a1 = As4[k*(ASTR/4) + ty*2 + 1];
            float4 b  = Bs4[k*16 + tx];
            float ar[8] = {a0.x,a0.y,a0.z,a0.w,a1.x,a1.y,a1.z,a1.w};
            float bc[4] = {b.x,b.y,b.z,b.w};
#pragma unroll
            for (int r = 0; r < 8; r++)
#pragma unroll
                for (int c = 0; c < 4; c++)
                    acc[r][c] += ar[r] * bc[c];
        }
    }

    // epilogue: multiply by gate, store g_go
    int nd = nd0 + tx*4;
    int n = nd >> 3, d = nd & 7;
#pragma unroll
    for (int r = 0; r < 8; r++) {
        size_t base = ((size_t)(i0 + ty*8 + r) * N_ + n) * CM_ + h*D_ + d;
        float4 gg = *reinterpret_cast<const float4*>(g_gate + base);
        float4 res;
        res.x = acc[r][0] * gg.x;
        res.y = acc[r][1] * gg.y;
        res.z = acc[r][2] * gg.z;
        res.w = acc[r][3] * gg.w;
        *reinterpret_cast<float4*>(g_go + base) = res;
    }
}

// ---------------------------------------------------------------------------
// Kernel D: out = (g*o) @ W_out^T   (thread-per-row matvec, W_out in shared)
// ---------------------------------------------------------------------------
__global__ void __launch_bounds__(128) k_out(
    const float* __restrict__ Wo, float* __restrict__ out)
{
    __shared__ float sW[CM_*CM_];
    int tid = threadIdx.x;
    for (int i = tid; i < CM_*CM_; i += 128) sW[i] = Wo[i];
    __syncthreads();

    size_t row = (size_t)blockIdx.x * 128 + tid;
    const float4* src = reinterpret_cast<const float4*>(g_go + row * CM_);
    float x[CM_];
#pragma unroll
    for (int i = 0; i < 16; i++) {
        float4 t = src[i];
        x[4*i+0] = t.x; x[4*i+1] = t.y; x[4*i+2] = t.z; x[4*i+3] = t.w;
    }
    float4* o4 = reinterpret_cast<float4*>(out + row * CM_);
    for (int o = 0; o < CM_; o += 4) {
        float a[4];
#pragma unroll
        for (int oo = 0; oo < 4; oo++) {
            const float4* w = reinterpret_cast<const float4*>(sW + (o+oo) * CM_);
            float acc = 0.f;
#pragma unroll
            for (int k = 0; k < 16; k++) {
                float4 t = w[k];
                acc += x[4*k+0]*t.x + x[4*k+1]*t.y + x[4*k+2]*t.z + x[4*k+3]*t.w;
            }
            a[oo] = acc;
        }
        float4 r4; r4.x = a[0]; r4.y = a[1]; r4.z = a[2]; r4.w = a[3];
        o4[o >> 2] = r4;
    }
}

// ---------------------------------------------------------------------------
// Launch
// ---------------------------------------------------------------------------
extern "C" void kernel_launch(void* const* d_in, const int* in_sizes, int n_in,
                              void* d_out, int out_size)
{
    const float* m_si   = (const float*)d_in[0];
    const float* z_ij   = (const float*)d_in[1];
    const float* ln_m_w = (const float*)d_in[2];
    const float* ln_m_b = (const float*)d_in[3];
    const float* ln_z_w = (const float*)d_in[4];
    const float* ln_z_b = (const float*)d_in[5];
    const float* W_v    = (const float*)d_in[6];
    const float* W_b    = (const float*)d_in[7];
    const float* W_g    = (const float*)d_in[8];
    const float* W_out  = (const float*)d_in[9];
    float* out = (float*)d_out;

    k_ln_vg  <<<SN_/128, 128>>>(m_si, ln_m_w, ln_m_b, W_v, W_g);
    k_bias   <<<SN_/8,   256>>>(z_ij, ln_z_w, ln_z_b, W_b);
    k_softmax<<<(H_*S_)/8, 256>>>();
    dim3 gC((N_*D_)/BN, S_/BM, H_);   // (64, 4, 8)
    k_pwa    <<<gC, 256>>>();
    k_out    <<<SN_/128, 128>>>(W_out, out);
}

// round 7
// speedup vs baseline: 1.3016x; 1.3016x over previous
#include <cuda_runtime.h>
#include <math.h>

// Problem shape (fixed by the dataset)
#define S_   512
#define N_   512
#define CM_  64
#define CZ_  128
#define H_   8
#define D_   8
#define SN_  (S_*N_)      // 262144 rows of m / out
#define EPS_ 1e-5f

// ---------------------------------------------------------------------------
// Scratch (device globals — no allocation allowed in kernel_launch)
// ---------------------------------------------------------------------------
__device__ float g_v   [SN_*CM_];   // v[j][n][c] (tf32-rounded)    64MB
__device__ float g_gate[SN_*CM_];   // sigmoid(m@Wg^T)[i][n][c]     64MB
__device__ float g_b   [H_*S_*S_];  // w[h][i][j] (tf32-rounded)     8MB
__device__ float g_go  [SN_*CM_];   // (g*o)[i][n][c]               64MB

// round-to-nearest tf32 (so the MMA's internal truncation is a no-op and
// quantization is unbiased)
__device__ __forceinline__ float tf32r(float x) {
    float y;
    asm("cvt.rna.tf32.f32 %0, %1;" : "=f"(y) : "f"(x));
    return y;
}

// ---------------------------------------------------------------------------
// Kernel A: per-row LayerNorm over CM, then v = mhat@Wv^T, gate = sigmoid(mhat@Wg^T)
// v output is tf32-rounded (consumed only by the tensor-core einsum)
// ---------------------------------------------------------------------------
__global__ void __launch_bounds__(128) k_ln_vg(
    const float* __restrict__ m, const float* __restrict__ lw,
    const float* __restrict__ lb, const float* __restrict__ Wv,
    const float* __restrict__ Wg)
{
    __shared__ float sWv[CM_*CM_];
    __shared__ float sWg[CM_*CM_];
    __shared__ float slw[CM_], slb[CM_];
    int tid = threadIdx.x;
    for (int i = tid; i < CM_*CM_; i += 128) { sWv[i] = Wv[i]; sWg[i] = Wg[i]; }
    if (tid < CM_) { slw[tid] = lw[tid]; slb[tid] = lb[tid]; }
    __syncthreads();

    size_t row = (size_t)blockIdx.x * 128 + tid;
    const float4* src = reinterpret_cast<const float4*>(m + row * CM_);
    float x[CM_];
    float s = 0.f, s2 = 0.f;
#pragma unroll
    for (int i = 0; i < 16; i++) {
        float4 t = src[i];
        x[4*i+0] = t.x; x[4*i+1] = t.y; x[4*i+2] = t.z; x[4*i+3] = t.w;
        s  += t.x + t.y + t.z + t.w;
        s2 += t.x*t.x + t.y*t.y + t.z*t.z + t.w*t.w;
    }
    float mu  = s * (1.f/CM_);
    float inv = rsqrtf(s2 * (1.f/CM_) - mu*mu + EPS_);
#pragma unroll
    for (int i = 0; i < CM_; i++) x[i] = (x[i] - mu) * inv * slw[i] + slb[i];

    float4* ov = reinterpret_cast<float4*>(g_v    + row * CM_);
    float4* og = reinterpret_cast<float4*>(g_gate + row * CM_);
    for (int o = 0; o < CM_; o += 4) {
        float av[4], ag[4];
#pragma unroll
        for (int oo = 0; oo < 4; oo++) {
            const float4* wv = reinterpret_cast<const float4*>(sWv + (o+oo) * CM_);
            const float4* wg = reinterpret_cast<const float4*>(sWg + (o+oo) * CM_);
            float a0 = 0.f, a1 = 0.f;
#pragma unroll
            for (int k = 0; k < 16; k++) {
                float4 w1 = wv[k];
                a0 += x[4*k+0]*w1.x + x[4*k+1]*w1.y + x[4*k+2]*w1.z + x[4*k+3]*w1.w;
                float4 w2 = wg[k];
                a1 += x[4*k+0]*w2.x + x[4*k+1]*w2.y + x[4*k+2]*w2.z + x[4*k+3]*w2.w;
            }
            av[oo] = tf32r(a0);                  // B operand of MMA: round here
            ag[oo] = 1.f / (1.f + __expf(-a1));  // sigmoid (stays fp32)
        }
        float4 v4; v4.x = av[0]; v4.y = av[1]; v4.z = av[2]; v4.w = av[3];
        float4 g4; g4.x = ag[0]; g4.y = ag[1]; g4.z = ag[2]; g4.w = ag[3];
        ov[o >> 2] = v4;
        og[o >> 2] = g4;
    }
}

// ---------------------------------------------------------------------------
// Kernel B: b[h][i][j] = LN(z[i][j][:]) . W_b[h][:]   (one warp per (i,j))
// ---------------------------------------------------------------------------
__global__ void __launch_bounds__(256) k_bias(
    const float* __restrict__ z, const float* __restrict__ lw,
    const float* __restrict__ lb, const float* __restrict__ Wb)
{
    __shared__ float sWb[H_*CZ_];
    __shared__ float slw[CZ_], slb[CZ_];
    int tid = threadIdx.x;
    for (int i = tid; i < H_*CZ_; i += 256) sWb[i] = Wb[i];
    if (tid < CZ_) { slw[tid] = lw[tid]; slb[tid] = lb[tid]; }
    __syncthreads();

    int lane = tid & 31;
    size_t row = (size_t)blockIdx.x * 8 + (tid >> 5);   // i*512 + j
    float4 t = reinterpret_cast<const float4*>(z + row * CZ_)[lane];
    float s  = t.x + t.y + t.z + t.w;
    float s2 = t.x*t.x + t.y*t.y + t.z*t.z + t.w*t.w;
#pragma unroll
    for (int o = 16; o; o >>= 1) {
        s  += __shfl_xor_sync(0xffffffffu, s,  o);
        s2 += __shfl_xor_sync(0xffffffffu, s2, o);
    }
    float mu  = s * (1.f/CZ_);
    float inv = rsqrtf(s2 * (1.f/CZ_) - mu*mu + EPS_);
    int c = lane * 4;
    float x0 = (t.x - mu) * inv * slw[c+0] + slb[c+0];
    float x1 = (t.y - mu) * inv * slw[c+1] + slb[c+1];
    float x2 = (t.z - mu) * inv * slw[c+2] + slb[c+2];
    float x3 = (t.w - mu) * inv * slw[c+3] + slb[c+3];

    float p[H_];
#pragma unroll
    for (int h = 0; h < H_; h++) {
        const float* w = sWb + h * CZ_ + c;
        p[h] = x0*w[0] + x1*w[1] + x2*w[2] + x3*w[3];
    }
#pragma unroll
    for (int o = 16; o; o >>= 1) {
#pragma unroll
        for (int h = 0; h < H_; h++)
            p[h] += __shfl_xor_sync(0xffffffffu, p[h], o);
    }
    if (lane < H_) g_b[(size_t)lane * (S_*S_) + row] = p[lane];
}

// ---------------------------------------------------------------------------
// Kernel B2: in-place softmax over j for each (h,i) row of g_b (512 elements)
// output tf32-rounded (consumed only as the A operand of the MMA)
// ---------------------------------------------------------------------------
__global__ void __launch_bounds__(256) k_softmax()
{
    int lane = threadIdx.x & 31;
    size_t r = (size_t)blockIdx.x * 8 + (threadIdx.x >> 5);   // h*S + i
    float4* p = reinterpret_cast<float4*>(g_b + r * S_);
    float4 v[4];
    float mx = -1e30f;
#pragma unroll
    for (int q = 0; q < 4; q++) {
        v[q] = p[q*32 + lane];
        mx = fmaxf(mx, fmaxf(fmaxf(v[q].x, v[q].y), fmaxf(v[q].z, v[q].w)));
    }
#pragma unroll
    for (int o = 16; o; o >>= 1) mx = fmaxf(mx, __shfl_xor_sync(0xffffffffu, mx, o));
    float sum = 0.f;
#pragma unroll
    for (int q = 0; q < 4; q++) {
        v[q].x = __expf(v[q].x - mx); v[q].y = __expf(v[q].y - mx);
        v[q].z = __expf(v[q].z - mx); v[q].w = __expf(v[q].w - mx);
        sum += v[q].x + v[q].y + v[q].z + v[q].w;
    }
#pragma unroll
    for (int o = 16; o; o >>= 1) sum += __shfl_xor_sync(0xffffffffu, sum, o);
    float is = 1.f / sum;
#pragma unroll
    for (int q = 0; q < 4; q++) {
        v[q].x = tf32r(v[q].x * is); v[q].y = tf32r(v[q].y * is);
        v[q].z = tf32r(v[q].z * is); v[q].w = tf32r(v[q].w * is);
        p[q*32 + lane] = v[q];
    }
}

// ---------------------------------------------------------------------------
// Kernel C (tensor cores): per head h:
//   O_h[i][nd] = sum_j w[h][i][j] * v[j][n, h*8+d],  nd = n*8+d in [0,4096)
// tf32 mma.sync m16n8k8, 128x128x16 block tile, 8 warps (64x32 warp tile),
// 2-stage cp.async pipeline. Epilogue fuses sigmoid gate: g_go = gate * O.
// ---------------------------------------------------------------------------
#define TBM 128
#define TBN 128
#define TBK 16
#define AST 20      // As row stride (floats): g*20+t spans all 32 banks
#define BST 136     // Bs row stride (floats): 8t+g spans all 32 banks
#define NKT (S_/TBK)   // 32 k-tiles

#define CPA16(dst, src) \
    asm volatile("cp.async.ca.shared.global [%0], [%1], 16;\n" :: "r"(dst), "l"(src))
#define CPCOMMIT() asm volatile("cp.async.commit_group;\n" ::: "memory")
#define CPWAIT(n)  asm volatile("cp.async.wait_group %0;\n" :: "n"(n) : "memory")

#define MMA_TF32(d, a, b) \
    asm volatile("mma.sync.aligned.m16n8k8.row.col.f32.tf32.tf32.f32 " \
        "{%0,%1,%2,%3}, {%4,%5,%6,%7}, {%8,%9}, {%0,%1,%2,%3};" \
        : "+f"((d)[0]), "+f"((d)[1]), "+f"((d)[2]), "+f"((d)[3]) \
        : "r"((a)[0]), "r"((a)[1]), "r"((a)[2]), "r"((a)[3]), \
          "r"((b)[0]), "r"((b)[1]))

__global__ void __launch_bounds__(256, 2) k_pwa_tc()
{
    __shared__ float As[2][TBM*AST];   // [m][k]  128 x 16 (+pad)
    __shared__ float Bs[2][TBK*BST];   // [k][nd]  16 x 128 (+pad)

    int tid  = threadIdx.x;
    int wid  = tid >> 5, lane = tid & 31;
    int g    = lane >> 2, t = lane & 3;     // mma quad coords
    int wm   = wid & 1;                     // 2 warp rows  (64 m each)
    int wn   = wid >> 1;                    // 4 warp cols  (32 nd each)
    int h    = blockIdx.z;
    int i0   = blockIdx.y * TBM;
    int nd0  = blockIdx.x * TBN;

    const float* Ag = g_b + (size_t)h * (S_*S_);

    float acc[4][4][4];
#pragma unroll
    for (int mf = 0; mf < 4; mf++)
#pragma unroll
        for (int nf = 0; nf < 4; nf++)
#pragma unroll
            for (int q = 0; q < 4; q++) acc[mf][nf][q] = 0.f;

    // per-thread global->smem copy coords (2 x 16B for A, 2 x 16B for B)
    int amA[2], akA[2]; const float* asrcRow[2];
    int bjB[2], bnd4B[2];
#pragma unroll
    for (int q = 0; q < 2; q++) {
        int f = q*256 + tid;            // A: 512 float4s (128 x 4)
        amA[q] = f >> 2; akA[q] = (f & 3) * 4;
        asrcRow[q] = Ag + (size_t)(i0 + amA[q]) * S_ + akA[q];
        int fb = q*256 + tid;           // B: 512 float4s (16 x 32)
        bjB[q] = fb >> 5; bnd4B[q] = fb & 31;
    }
    int nbase0 = nd0 >> 3;              // nd0 multiple of 128 -> n offset

    unsigned sA[2][2], sB[2][2];
#pragma unroll
    for (int buf = 0; buf < 2; buf++)
#pragma unroll
        for (int q = 0; q < 2; q++) {
            sA[buf][q] = (unsigned)__cvta_generic_to_shared(
                &As[buf][amA[q]*AST + akA[q]]);
            sB[buf][q] = (unsigned)__cvta_generic_to_shared(
                &Bs[buf][bjB[q]*BST + bnd4B[q]*4]);
        }

    // ---- issue tile kt into buffer buf ----
    auto issue = [&](int kt, int buf) {
        int k0 = kt * TBK;
#pragma unroll
        for (int q = 0; q < 2; q++)
            CPA16(sA[buf][q], asrcRow[q] + k0);
#pragma unroll
        for (int q = 0; q < 2; q++) {
            int n = nbase0 + (bnd4B[q] >> 1);
            int d = (bnd4B[q] & 1) * 4;
            const float* src = g_v + (size_t)(k0 + bjB[q]) * (N_*CM_)
                                   + n*CM_ + h*D_ + d;
            CPA16(sB[buf][q], src);
        }
    };

    issue(0, 0); CPCOMMIT();

    for (int kt = 0; kt < NKT; kt++) {
        int buf = kt & 1;
        if (kt + 1 < NKT) { issue(kt + 1, buf ^ 1); CPCOMMIT(); CPWAIT(1); }
        else              { CPWAIT(0); }
        __syncthreads();

        const float* Ab = As[buf];
        const float* Bb = Bs[buf];
#pragma unroll
        for (int kk = 0; kk < 2; kk++) {     // two k8 steps per 16-k tile
            unsigned a[4][4], b[4][2];
#pragma unroll
            for (int mf = 0; mf < 4; mf++) {
                const float* base = Ab + (wm*64 + mf*16 + g)*AST + kk*8 + t;
                a[mf][0] = __float_as_uint(base[0]);
                a[mf][1] = __float_as_uint(base[8*AST]);
                a[mf][2] = __float_as_uint(base[4]);
                a[mf][3] = __float_as_uint(base[8*AST + 4]);
            }
#pragma unroll
            for (int nf = 0; nf < 4; nf++) {
                const float* base = Bb + (kk*8 + t)*BST + wn*32 + nf*8 + g;
                b[nf][0] = __float_as_uint(base[0]);
                b[nf][1] = __float_as_uint(base[4*BST]);
            }
#pragma unroll
            for (int mf = 0; mf < 4; mf++)
#pragma unroll
                for (int nf = 0; nf < 4; nf++)
                    MMA_TF32(acc[mf][nf], a[mf], b[nf]);
        }
        __syncthreads();
    }

    // ---- epilogue: gate-multiply + store ----
#pragma unroll
    for (int mf = 0; mf < 4; mf++) {
        int i = i0 + wm*64 + mf*16 + g;
#pragma unroll
        for (int nf = 0; nf < 4; nf++) {
            int nd = nd0 + wn*32 + nf*8 + t*2;     // even -> float2 ok
            size_t base = ((size_t)i * N_ + (nd >> 3)) * CM_ + h*D_ + (nd & 7);
            float2 g0 = *reinterpret_cast<const float2*>(g_gate + base);
            float2 r0;
            r0.x = acc[mf][nf][0] * g0.x;
            r0.y = acc[mf][nf][1] * g0.y;
            *reinterpret_cast<float2*>(g_go + base) = r0;
            size_t base2 = base + (size_t)8 * N_ * CM_;   // rows i+8
            float2 g1 = *reinterpret_cast<const float2*>(g_gate + base2);
            float2 r1;
            r1.x = acc[mf][nf][2] * g1.x;
            r1.y = acc[mf][nf][3] * g1.y;
            *reinterpret_cast<float2*>(g_go + base2) = r1;
        }
    }
}

// ---------------------------------------------------------------------------
// Kernel D: out = (g*o) @ W_out^T   (thread-per-row matvec, W_out in shared)
// ---------------------------------------------------------------------------
__global__ void __launch_bounds__(128) k_out(
    const float* __restrict__ Wo, float* __restrict__ out)
{
    __shared__ float sW[CM_*CM_];
    int tid = threadIdx.x;
    for (int i = tid; i < CM_*CM_; i += 128) sW[i] = Wo[i];
    __syncthreads();

    size_t row = (size_t)blockIdx.x * 128 + tid;
    const float4* src = reinterpret_cast<const float4*>(g_go + row * CM_);
    float x[CM_];
#pragma unroll
    for (int i = 0; i < 16; i++) {
        float4 t = src[i];
        x[4*i+0] = t.x; x[4*i+1] = t.y; x[4*i+2] = t.z; x[4*i+3] = t.w;
    }
    float4* o4 = reinterpret_cast<float4*>(out + row * CM_);
    for (int o = 0; o < CM_; o += 4) {
        float a[4];
#pragma unroll
        for (int oo = 0; oo < 4; oo++) {
            const float4* w = reinterpret_cast<const float4*>(sW + (o+oo) * CM_);
            float acc = 0.f;
#pragma unroll
            for (int k = 0; k < 16; k++) {
                float4 t = w[k];
                acc += x[4*k+0]*t.x + x[4*k+1]*t.y + x[4*k+2]*t.z + x[4*k+3]*t.w;
            }
            a[oo] = acc;
        }
        float4 r4; r4.x = a[0]; r4.y = a[1]; r4.z = a[2]; r4.w = a[3];
        o4[o >> 2] = r4;
    }
}

// ---------------------------------------------------------------------------
// Launch
// ---------------------------------------------------------------------------
extern "C" void kernel_launch(void* const* d_in, const int* in_sizes, int n_in,
                              void* d_out, int out_size)
{
    const float* m_si   = (const float*)d_in[0];
    const float* z_ij   = (const float*)d_in[1];
    const float* ln_m_w = (const float*)d_in[2];
    const float* ln_m_b = (const float*)d_in[3];
    const float* ln_z_w = (const float*)d_in[4];
    const float* ln_z_b = (const float*)d_in[5];
    const float* W_v    = (const float*)d_in[6];
    const float* W_b    = (const float*)d_in[7];
    const float* W_g    = (const float*)d_in[8];
    const float* W_out  = (const float*)d_in[9];
    float* out = (float*)d_out;

    k_ln_vg  <<<SN_/128, 128>>>(m_si, ln_m_w, ln_m_b, W_v, W_g);
    k_bias   <<<SN_/8,   256>>>(z_ij, ln_z_w, ln_z_b, W_b);
    k_softmax<<<(H_*S_)/8, 256>>>();
    dim3 gC((N_*D_)/TBN, S_/TBM, H_);   // (32, 4, 8) = 1024 blocks
    k_pwa_tc <<<gC, 256>>>();
    k_out    <<<SN_/128, 128>>>(W_out, out);
}

// round 8
// speedup vs baseline: 1.8415x; 1.4149x over previous
#include <cuda_runtime.h>
#include <math.h>

// Problem shape (fixed by the dataset)
#define S_   512
#define N_   512
#define CM_  64
#define CZ_  128
#define H_   8
#define D_   8
#define SN_  (S_*N_)      // 262144 rows of m / out
#define EPS_ 1e-5f

// ---------------------------------------------------------------------------
// Scratch (device globals — no allocation allowed in kernel_launch)
// ---------------------------------------------------------------------------
// v in HEAD-MAJOR layout: g_v2[h][j][nd], nd = n*8+d  (tf32-rounded)   64MB
__device__ float g_v2  [H_*S_*N_*D_];
__device__ float g_gate[SN_*CM_];   // sigmoid(m@Wg^T)[i][n][c] fp32   64MB
__device__ float g_b   [H_*S_*S_];  // w[h][i][j] (tf32-rounded)        8MB
__device__ float g_go  [SN_*CM_];   // (g*o)[i][n][c] (tf32-rounded)   64MB

// round-to-nearest tf32 (MMA's internal truncation becomes a no-op; unbiased)
__device__ __forceinline__ float tf32r(float x) {
    float y;
    asm("cvt.rna.tf32.f32 %0, %1;" : "=f"(y) : "f"(x));
    return y;
}

#define CPA16(dst, src) \
    asm volatile("cp.async.ca.shared.global [%0], [%1], 16;\n" :: "r"(dst), "l"(src))
#define CPCOMMIT() asm volatile("cp.async.commit_group;\n" ::: "memory")
#define CPWAIT(n)  asm volatile("cp.async.wait_group %0;\n" :: "n"(n) : "memory")

#define MMA_TF32(d, a, b) \
    asm volatile("mma.sync.aligned.m16n8k8.row.col.f32.tf32.tf32.f32 " \
        "{%0,%1,%2,%3}, {%4,%5,%6,%7}, {%8,%9}, {%0,%1,%2,%3};" \
        : "+f"((d)[0]), "+f"((d)[1]), "+f"((d)[2]), "+f"((d)[3]) \
        : "r"((a)[0]), "r"((a)[1]), "r"((a)[2]), "r"((a)[3]), \
          "r"((b)[0]), "r"((b)[1]))

// ---------------------------------------------------------------------------
// Kernel A (tensor cores): LayerNorm over CM, then
//   [v | gate] = x_hat @ [Wv^T | Wg^T]      (128 rows x 128 outs x K=64)
// v written tf32-rounded in head-major g_v2[h][j][nd]; gate fp32 row-major.
// A operand staged tf32 in smem [k][m]; W fragments via LDG (L1/L2 resident).
// ---------------------------------------------------------------------------
#define LN_AST 136   // [k][m] stride: (8t+g) spans distinct banks

__global__ void __launch_bounds__(256) k_ln_vg_tc(
    const float* __restrict__ m, const float* __restrict__ lw,
    const float* __restrict__ lb, const float* __restrict__ Wv,
    const float* __restrict__ Wg)
{
    __shared__ float As[CM_ * LN_AST];   // x_hat tf32, indexed [k][m]
    __shared__ float slw[CM_], slb[CM_];
    int tid = threadIdx.x, wid = tid >> 5, lane = tid & 31;
    int g = lane >> 2, t = lane & 3;
    int wm = wid & 1;          // 2 warp rows (64 m each)
    int wn = wid >> 1;         // 4 warp cols (32 outs each): 0,1->Wv  2,3->Wg
    size_t r0 = (size_t)blockIdx.x * 128;

    if (tid < CM_) { slw[tid] = lw[tid]; slb[tid] = lb[tid]; }
    __syncthreads();

    if (tid < 128) {
        size_t row = r0 + tid;
        const float4* src = reinterpret_cast<const float4*>(m + row * CM_);
        float x[CM_];
        float s = 0.f, s2 = 0.f;
#pragma unroll
        for (int i = 0; i < 16; i++) {
            float4 v4 = src[i];
            x[4*i+0] = v4.x; x[4*i+1] = v4.y; x[4*i+2] = v4.z; x[4*i+3] = v4.w;
            s  += v4.x + v4.y + v4.z + v4.w;
            s2 += v4.x*v4.x + v4.y*v4.y + v4.z*v4.z + v4.w*v4.w;
        }
        float mu  = s * (1.f/CM_);
        float inv = rsqrtf(s2 * (1.f/CM_) - mu*mu + EPS_);
#pragma unroll
        for (int k = 0; k < CM_; k++)
            As[k * LN_AST + tid] = tf32r((x[k] - mu) * inv * slw[k] + slb[k]);
    }
    __syncthreads();

    float acc[4][4][4];
#pragma unroll
    for (int mf = 0; mf < 4; mf++)
#pragma unroll
        for (int nf = 0; nf < 4; nf++)
#pragma unroll
            for (int q = 0; q < 4; q++) acc[mf][nf][q] = 0.f;

    const float* W = (wn < 2) ? Wv : Wg;
    int nbase = (wn & 1) * 32;

#pragma unroll
    for (int kk = 0; kk < 8; kk++) {
        unsigned a[4][4], b[4][2];
#pragma unroll
        for (int mf = 0; mf < 4; mf++) {
            const float* base = As + (kk*8 + t) * LN_AST + wm*64 + mf*16 + g;
            a[mf][0] = __float_as_uint(base[0]);
            a[mf][1] = __float_as_uint(base[8]);
            a[mf][2] = __float_as_uint(base[4 * LN_AST]);
            a[mf][3] = __float_as_uint(base[4 * LN_AST + 8]);
        }
#pragma unroll
        for (int nf = 0; nf < 4; nf++) {
            const float* wp = W + (nbase + nf*8 + g) * CM_ + kk*8 + t;
            b[nf][0] = __float_as_uint(tf32r(wp[0]));
            b[nf][1] = __float_as_uint(tf32r(wp[4]));
        }
#pragma unroll
        for (int mf = 0; mf < 4; mf++)
#pragma unroll
            for (int nf = 0; nf < 4; nf++)
                MMA_TF32(acc[mf][nf], a[mf], b[nf]);
    }

    // epilogue: block rows share one j (128 rows within a 512-row j group)
    int j  = (int)(r0 >> 9);
    int n0 = (int)(r0 & 511);
#pragma unroll
    for (int mf = 0; mf < 4; mf++) {
        int mrow = wm*64 + mf*16 + g;      // local row (and +8)
#pragma unroll
        for (int nf = 0; nf < 4; nf++) {
            int c = nbase + nf*8 + t*2;    // 0..63 within Wv or Wg space
            if (wn < 2) {
                // v -> g_v2[h][j][ (n0+mrow)*8 + d ], h=c>>3, d=c&7 (d,d+1 pair)
                int h = c >> 3, d = c & 7;
                size_t base = ((size_t)h * S_ + j) * (N_*D_);
                float2 r0v, r1v;
                r0v.x = tf32r(acc[mf][nf][0]); r0v.y = tf32r(acc[mf][nf][1]);
                r1v.x = tf32r(acc[mf][nf][2]); r1v.y = tf32r(acc[mf][nf][3]);
                *reinterpret_cast<float2*>(g_v2 + base + (n0+mrow)*D_ + d)   = r0v;
                *reinterpret_cast<float2*>(g_v2 + base + (n0+mrow+8)*D_ + d) = r1v;
            } else {
                // gate -> g_gate[row][c] fp32
                size_t row = r0 + mrow;
                float2 g0, g1;
                g0.x = 1.f/(1.f + __expf(-acc[mf][nf][0]));
                g0.y = 1.f/(1.f + __expf(-acc[mf][nf][1]));
                g1.x = 1.f/(1.f + __expf(-acc[mf][nf][2]));
                g1.y = 1.f/(1.f + __expf(-acc[mf][nf][3]));
                *reinterpret_cast<float2*>(g_gate + row*CM_ + c)       = g0;
                *reinterpret_cast<float2*>(g_gate + (row+8)*CM_ + c)   = g1;
            }
        }
    }
}

// ---------------------------------------------------------------------------
// Kernel B: b[h][i][j] = LN(z[i][j][:]) . W_b[h][:]   (one warp per (i,j))
// ---------------------------------------------------------------------------
__global__ void __launch_bounds__(256) k_bias(
    const float* __restrict__ z, const float* __restrict__ lw,
    const float* __restrict__ lb, const float* __restrict__ Wb)
{
    __shared__ float sWb[H_*CZ_];
    __shared__ float slw[CZ_], slb[CZ_];
    int tid = threadIdx.x;
    for (int i = tid; i < H_*CZ_; i += 256) sWb[i] = Wb[i];
    if (tid < CZ_) { slw[tid] = lw[tid]; slb[tid] = lb[tid]; }
    __syncthreads();

    int lane = tid & 31;
    size_t row = (size_t)blockIdx.x * 8 + (tid >> 5);   // i*512 + j
    float4 t = reinterpret_cast<const float4*>(z + row * CZ_)[lane];
    float s  = t.x + t.y + t.z + t.w;
    float s2 = t.x*t.x + t.y*t.y + t.z*t.z + t.w*t.w;
#pragma unroll
    for (int o = 16; o; o >>= 1) {
        s  += __shfl_xor_sync(0xffffffffu, s,  o);
        s2 += __shfl_xor_sync(0xffffffffu, s2, o);
    }
    float mu  = s * (1.f/CZ_);
    float inv = rsqrtf(s2 * (1.f/CZ_) - mu*mu + EPS_);
    int c = lane * 4;
    float x0 = (t.x - mu) * inv * slw[c+0] + slb[c+0];
    float x1 = (t.y - mu) * inv * slw[c+1] + slb[c+1];
    float x2 = (t.z - mu) * inv * slw[c+2] + slb[c+2];
    float x3 = (t.w - mu) * inv * slw[c+3] + slb[c+3];

    float p[H_];
#pragma unroll
    for (int h = 0; h < H_; h++) {
        const float* w = sWb + h * CZ_ + c;
        p[h] = x0*w[0] + x1*w[1] + x2*w[2] + x3*w[3];
    }
#pragma unroll
    for (int o = 16; o; o >>= 1) {
#pragma unroll
        for (int h = 0; h < H_; h++)
            p[h] += __shfl_xor_sync(0xffffffffu, p[h], o);
    }
    if (lane < H_) g_b[(size_t)lane * (S_*S_) + row] = p[lane];
}

// ---------------------------------------------------------------------------
// Kernel B2: in-place softmax over j per (h,i) row of g_b; tf32-rounded out
// ---------------------------------------------------------------------------
__global__ void __launch_bounds__(256) k_softmax()
{
    int lane = threadIdx.x & 31;
    size_t r = (size_t)blockIdx.x * 8 + (threadIdx.x >> 5);   // h*S + i
    float4* p = reinterpret_cast<float4*>(g_b + r * S_);
    float4 v[4];
    float mx = -1e30f;
#pragma unroll
    for (int q = 0; q < 4; q++) {
        v[q] = p[q*32 + lane];
        mx = fmaxf(mx, fmaxf(fmaxf(v[q].x, v[q].y), fmaxf(v[q].z, v[q].w)));
    }
#pragma unroll
    for (int o = 16; o; o >>= 1) mx = fmaxf(mx, __shfl_xor_sync(0xffffffffu, mx, o));
    float sum = 0.f;
#pragma unroll
    for (int q = 0; q < 4; q++) {
        v[q].x = __expf(v[q].x - mx); v[q].y = __expf(v[q].y - mx);
        v[q].z = __expf(v[q].z - mx); v[q].w = __expf(v[q].w - mx);
        sum += v[q].x + v[q].y + v[q].z + v[q].w;
    }
#pragma unroll
    for (int o = 16; o; o >>= 1) sum += __shfl_xor_sync(0xffffffffu, sum, o);
    float is = 1.f / sum;
#pragma unroll
    for (int q = 0; q < 4; q++) {
        v[q].x = tf32r(v[q].x * is); v[q].y = tf32r(v[q].y * is);
        v[q].z = tf32r(v[q].z * is); v[q].w = tf32r(v[q].w * is);
        p[q*32 + lane] = v[q];
    }
}

// ---------------------------------------------------------------------------
// Kernel C (tensor cores): per head h:
//   O_h[i][nd] = sum_j w[h][i][j] * v2[h][j][nd],  nd in [0,4096)
// tf32 mma m16n8k8, 128x128x16 tile, 2-stage cp.async. B loads contiguous
// (head-major v2). Epilogue: g_go = tf32(gate * O).
// ---------------------------------------------------------------------------
#define TBM 128
#define TBN 128
#define TBK 16
#define AST 20
#define BST 136
#define NKT (S_/TBK)

__global__ void __launch_bounds__(256, 2) k_pwa_tc()
{
    __shared__ float As[2][TBM*AST];   // [m][k]
    __shared__ float Bs[2][TBK*BST];   // [k][nd]

    int tid  = threadIdx.x;
    int wid  = tid >> 5, lane = tid & 31;
    int g    = lane >> 2, t = lane & 3;
    int wm   = wid & 1;
    int wn   = wid >> 1;
    int h    = blockIdx.z;
    int i0   = blockIdx.y * TBM;
    int nd0  = blockIdx.x * TBN;

    const float* Ag = g_b  + (size_t)h * (S_*S_);
    const float* Vh = g_v2 + (size_t)h * (S_*N_*D_);

    float acc[4][4][4];
#pragma unroll
    for (int mf = 0; mf < 4; mf++)
#pragma unroll
        for (int nf = 0; nf < 4; nf++)
#pragma unroll
            for (int q = 0; q < 4; q++) acc[mf][nf][q] = 0.f;

    int amA[2], akA[2]; const float* asrcRow[2];
    int bjB[2], bc4B[2];
#pragma unroll
    for (int q = 0; q < 2; q++) {
        int f = q*256 + tid;            // A: 512 float4s (128 x 4)
        amA[q] = f >> 2; akA[q] = (f & 3) * 4;
        asrcRow[q] = Ag + (size_t)(i0 + amA[q]) * S_ + akA[q];
        int fb = q*256 + tid;           // B: 512 float4s (16 x 32) — contiguous rows
        bjB[q] = fb >> 5; bc4B[q] = fb & 31;
    }

    unsigned sA[2][2], sB[2][2];
#pragma unroll
    for (int buf = 0; buf < 2; buf++)
#pragma unroll
        for (int q = 0; q < 2; q++) {
            sA[buf][q] = (unsigned)__cvta_generic_to_shared(
                &As[buf][amA[q]*AST + akA[q]]);
            sB[buf][q] = (unsigned)__cvta_generic_to_shared(
                &Bs[buf][bjB[q]*BST + bc4B[q]*4]);
        }

    auto issue = [&](int kt, int buf) {
        int k0 = kt * TBK;
#pragma unroll
        for (int q = 0; q < 2; q++)
            CPA16(sA[buf][q], asrcRow[q] + k0);
#pragma unroll
        for (int q = 0; q < 2; q++) {
            const float* src = Vh + (size_t)(k0 + bjB[q]) * (N_*D_)
                                  + nd0 + bc4B[q]*4;
            CPA16(sB[buf][q], src);
        }
    };

    issue(0, 0); CPCOMMIT();

    for (int kt = 0; kt < NKT; kt++) {
        int buf = kt & 1;
        if (kt + 1 < NKT) { issue(kt + 1, buf ^ 1); CPCOMMIT(); CPWAIT(1); }
        else              { CPWAIT(0); }
        __syncthreads();

        const float* Ab = As[buf];
        const float* Bb = Bs[buf];
#pragma unroll
        for (int kk = 0; kk < 2; kk++) {
            unsigned a[4][4], b[4][2];
#pragma unroll
            for (int mf = 0; mf < 4; mf++) {
                const float* base = Ab + (wm*64 + mf*16 + g)*AST + kk*8 + t;
                a[mf][0] = __float_as_uint(base[0]);
                a[mf][1] = __float_as_uint(base[8*AST]);
                a[mf][2] = __float_as_uint(base[4]);
                a[mf][3] = __float_as_uint(base[8*AST + 4]);
            }
#pragma unroll
            for (int nf = 0; nf < 4; nf++) {
                const float* base = Bb + (kk*8 + t)*BST + wn*32 + nf*8 + g;
                b[nf][0] = __float_as_uint(base[0]);
                b[nf][1] = __float_as_uint(base[4*BST]);
            }
#pragma unroll
            for (int mf = 0; mf < 4; mf++)
#pragma unroll
                for (int nf = 0; nf < 4; nf++)
                    MMA_TF32(acc[mf][nf], a[mf], b[nf]);
        }
        __syncthreads();
    }

    // epilogue: gate-multiply, tf32-round (g_go feeds the tf32 out-GEMM)
#pragma unroll
    for (int mf = 0; mf < 4; mf++) {
        int i = i0 + wm*64 + mf*16 + g;
#pragma unroll
        for (int nf = 0; nf < 4; nf++) {
            int nd = nd0 + wn*32 + nf*8 + t*2;
            size_t base = ((size_t)i * N_ + (nd >> 3)) * CM_ + h*D_ + (nd & 7);
            float2 g0 = *reinterpret_cast<const float2*>(g_gate + base);
            float2 r0;
            r0.x = tf32r(acc[mf][nf][0] * g0.x);
            r0.y = tf32r(acc[mf][nf][1] * g0.y);
            *reinterpret_cast<float2*>(g_go + base) = r0;
            size_t base2 = base + (size_t)8 * N_ * CM_;
            float2 g1 = *reinterpret_cast<const float2*>(g_gate + base2);
            float2 r1;
            r1.x = tf32r(acc[mf][nf][2] * g1.x);
            r1.y = tf32r(acc[mf][nf][3] * g1.y);
            *reinterpret_cast<float2*>(g_go + base2) = r1;
        }
    }
}

// ---------------------------------------------------------------------------
// Kernel D (tensor cores): out = g_go @ W_out^T   (128 rows x 64 x K=64)
// g_go already tf32-rounded; W_out fragments via LDG + cvt.
// ---------------------------------------------------------------------------
#define OUT_AST 68   // [m][k] stride: (4g+t) distinct banks

__global__ void __launch_bounds__(256) k_out_tc(
    const float* __restrict__ Wo, float* __restrict__ out)
{
    __shared__ float As[128 * OUT_AST];
    int tid = threadIdx.x, wid = tid >> 5, lane = tid & 31;
    int g = lane >> 2, t = lane & 3;
    int wm = wid & 1;          // 2 warp rows (64 m)
    int wn = wid >> 1;         // 4 warp cols (16 n each)
    size_t r0 = (size_t)blockIdx.x * 128;

    // stage g_go tile (128 x 64) -> smem, coalesced
#pragma unroll
    for (int q = 0; q < 8; q++) {
        int f = q*256 + tid;             // 2048 float4s
        int mrow = f >> 4, k4 = (f & 15) * 4;
        unsigned dst = (unsigned)__cvta_generic_to_shared(
            &As[mrow * OUT_AST + k4]);
        CPA16(dst, g_go + (r0 + mrow) * CM_ + k4);
    }
    CPCOMMIT(); CPWAIT(0);
    __syncthreads();

    float acc[4][2][4];
#pragma unroll
    for (int mf = 0; mf < 4; mf++)
#pragma unroll
        for (int nf = 0; nf < 2; nf++)
#pragma unroll
            for (int q = 0; q < 4; q++) acc[mf][nf][q] = 0.f;

#pragma unroll
    for (int kk = 0; kk < 8; kk++) {
        unsigned a[4][4], b[2][2];
#pragma unroll
        for (int mf = 0; mf < 4; mf++) {
            const float* base = As + (wm*64 + mf*16 + g) * OUT_AST + kk*8 + t;
            a[mf][0] = __float_as_uint(base[0]);
            a[mf][1] = __float_as_uint(base[8 * OUT_AST]);
            a[mf][2] = __float_as_uint(base[4]);
            a[mf][3] = __float_as_uint(base[8 * OUT_AST + 4]);
        }
#pragma unroll
        for (int nf = 0; nf < 2; nf++) {
            const float* wp = Wo + (wn*16 + nf*8 + g) * CM_ + kk*8 + t;
            b[nf][0] = __float_as_uint(tf32r(wp[0]));
            b[nf][1] = __float_as_uint(tf32r(wp[4]));
        }
#pragma unroll
        for (int mf = 0; mf < 4; mf++)
#pragma unroll
            for (int nf = 0; nf < 2; nf++)
                MMA_TF32(acc[mf][nf], a[mf], b[nf]);
    }

#pragma unroll
    for (int mf = 0; mf < 4; mf++) {
        size_t row = r0 + wm*64 + mf*16 + g;
#pragma unroll
        for (int nf = 0; nf < 2; nf++) {
            int c = wn*16 + nf*8 + t*2;
            float2 o0, o1;
            o0.x = acc[mf][nf][0]; o0.y = acc[mf][nf][1];
            o1.x = acc[mf][nf][2]; o1.y = acc[mf][nf][3];
            *reinterpret_cast<float2*>(out + row*CM_ + c)     = o0;
            *reinterpret_cast<float2*>(out + (row+8)*CM_ + c) = o1;
        }
    }
}

// ---------------------------------------------------------------------------
// Launch
// ---------------------------------------------------------------------------
extern "C" void kernel_launch(void* const* d_in, const int* in_sizes, int n_in,
                              void* d_out, int out_size)
{
    const float* m_si   = (const float*)d_in[0];
    const float* z_ij   = (const float*)d_in[1];
    const float* ln_m_w = (const float*)d_in[2];
    const float* ln_m_b = (const float*)d_in[3];
    const float* ln_z_w = (const float*)d_in[4];
    const float* ln_z_b = (const float*)d_in[5];
    const float* W_v    = (const float*)d_in[6];
    const float* W_b    = (const float*)d_in[7];
    const float* W_g    = (const float*)d_in[8];
    const float* W_out  = (const float*)d_in[9];
    float* out = (float*)d_out;

    k_ln_vg_tc<<<SN_/128, 256>>>(m_si, ln_m_w, ln_m_b, W_v, W_g);
    k_bias    <<<SN_/8,   256>>>(z_ij, ln_z_w, ln_z_b, W_b);
    k_softmax <<<(H_*S_)/8, 256>>>();
    dim3 gC((N_*D_)/TBN, S_/TBM, H_);   // (32, 4, 8) = 1024 blocks
    k_pwa_tc  <<<gC, 256>>>();
    k_out_tc  <<<SN_/128, 256>>>(W_out, out);
}